// round 2
// baseline (speedup 1.0000x reference)
#include <cuda_runtime.h>
#include <math.h>

// Problem constants
#define C_CH   192
#define HW     56
#define NPIX   3136      // 56*56
#define NBATCH 64
#define N4TOT  9633792   // 64*192*3136/4

__constant__ float c_lowx[32] = {0,0,1,1,0,2,2,1,2,0,3,4,0,1,3,0,1,2,3,4,5,0,1,2,3,4,5,6,1,2,3,4};
__constant__ float c_lowy[32] = {0,1,0,1,2,0,1,2,2,3,0,0,4,3,1,5,4,3,2,1,0,6,5,4,3,2,1,0,6,5,4,3};

// Scratch (no allocations allowed -> __device__ globals)
__device__ float g_part[56 * 32];        // per-row gate partial sums (n=0 only)
__device__ float g_xp[64 * 192 * 49];    // adaptive-avg-pooled x (means)
__device__ float g_w1dT[192 * 192];      // transposed center tap of w1d: [c][o]
__device__ float g_scale[64 * 192];      // final per-(n,c) scale

// ---------------------------------------------------------------------------
// Gate kernel: ONLY batch element 0 matters (reference uses xg[0] exclusively).
// One block per image row h (56 blocks). 448 threads: px = t%56, q = t/56
// gives 8 channel-slices of 24 channels each. Per-pixel 32-wide conv partials
// are combined via padded shared atomics, then BN+ReLU+row-sum -> g_part.
// ---------------------------------------------------------------------------
__global__ __launch_bounds__(448) void gate_kernel(
    const float* __restrict__ x, const float* __restrict__ wg1,
    const float* __restrict__ bng, const float* __restrict__ bnb,
    const float* __restrict__ bnm, const float* __restrict__ bnv)
{
    __shared__ float sw[192 * 32];     // sw[c*32+o] = wg1[o][c]
    __shared__ float sconv[56 * 33];   // padded stride 33 -> conflict-free atomics

    int t = threadIdx.x;
    for (int i = t; i < 192 * 32; i += 448) {
        int c = i >> 5, o = i & 31;
        sw[i] = wg1[o * 192 + c];
    }
    for (int i = t; i < 56 * 33; i += 448) sconv[i] = 0.0f;
    __syncthreads();

    int px = t % 56;
    int q  = t / 56;                  // 0..7
    const float* xr = x + blockIdx.x * 56 + px;   // n=0, row=blockIdx.x

    float acc[32];
#pragma unroll
    for (int u = 0; u < 32; u++) acc[u] = 0.0f;

    int c0 = q * 24;
#pragma unroll 4
    for (int c = c0; c < c0 + 24; c++) {
        float xv = __ldg(xr + c * NPIX);
        const float* w = sw + c * 32;
#pragma unroll
        for (int u = 0; u < 32; u++) acc[u] = fmaf(w[u], xv, acc[u]);
    }
    float* dst = sconv + px * 33;
#pragma unroll
    for (int u = 0; u < 32; u++) atomicAdd(dst + u, acc[u]);
    __syncthreads();

    if (t < 32) {
        int o = t;
        float sc = bng[o] / sqrtf(bnv[o] + 1e-5f);
        float sh = bnb[o] - bnm[o] * sc;
        float s = 0.0f;
        for (int p = 0; p < 56; p++) {
            float v = fmaf(sconv[p * 33 + o], sc, sh);
            s += fmaxf(v, 0.0f);
        }
        g_part[blockIdx.x * 32 + o] = s;
    }
}

// ---------------------------------------------------------------------------
// Pool kernel: streams all of x once. One thread per pooling cell (n,c,i,j):
// sums an 8x8 block via 16 float4 loads. Also copies the conv1d center tap
// into a transposed, coalesce-friendly layout (first 144 blocks).
// 2352 blocks * 256 threads = 602112 cells exactly.
// ---------------------------------------------------------------------------
__global__ __launch_bounds__(256) void pool_kernel(
    const float* __restrict__ x, const float* __restrict__ w1d)
{
    int b = blockIdx.x, t = threadIdx.x;
    if (b < 144) {
        int i = b * 256 + t;
        if (i < 192 * 192) {
            int o = i % 192, cc = i / 192;
            g_w1dT[i] = w1d[o * 576 + cc * 3 + 1];  // [c][o] layout
        }
    }

    int cid = b * 256 + t;                 // = nc*49 + i7*7 + j  (xp linear index)
    int j   = cid % 7;
    int tmp = cid / 7;
    int i7  = tmp % 7;
    int nc  = tmp / 7;

    const float4* p = (const float4*)(x + (size_t)nc * NPIX + i7 * 8 * 56 + j * 8);
    float s = 0.0f;
#pragma unroll
    for (int r = 0; r < 8; r++) {
        float4 a = __ldg(p + r * 14);
        float4 c = __ldg(p + r * 14 + 1);
        s += (a.x + a.y + a.z + a.w) + (c.x + c.y + c.z + c.w);
    }
    g_xp[cid] = s * (1.0f / 64.0f);
}

// ---------------------------------------------------------------------------
// Scale kernel: one block per batch element (64 blocks, 192 threads).
// Each block redundantly computes xg0 -> param -> DCT basis -> filt selection,
// then yin[c] = <xp[n,c,:,:], filt[c]> , y = conv1d center-tap GEMV, BN, ReLU.
// ---------------------------------------------------------------------------
__global__ __launch_bounds__(192) void scale_kernel(
    const float* __restrict__ wg2, const float* __restrict__ bg2,
    const float* __restrict__ beta, const float* __restrict__ b1d,
    const float* __restrict__ bn1g, const float* __restrict__ bn1b,
    const float* __restrict__ bn1m, const float* __restrict__ bn1v)
{
    __shared__ float sg[32];
    __shared__ float sxg[32];
    __shared__ float sparam[33];
    __shared__ float sbasis[32 * 49];
    __shared__ float syin[192];

    int n = blockIdx.x, t = threadIdx.x;

    if (t < 32) {
        float s = 0.0f;
        for (int b = 0; b < 56; b++) s += g_part[b * 32 + t];
        sg[t] = s * (1.0f / 3136.0f);
    }
    __syncthreads();
    if (t < 32) {
        float a = bg2[t];
        for (int k = 0; k < 32; k++) a = fmaf(wg2[t * 32 + k], sg[k], a);
        sxg[t] = fmaxf(tanhf(a), 0.0f) + beta[0];
    }
    __syncthreads();
    if (t == 0) {
        float s = 0.0f;
        for (int i = 0; i < 32; i++) s += sxg[i];
        sparam[0] = 0.0f;
        float tot = 0.0f;
        for (int i = 1; i <= 31; i++) {
            float pv = rintf(sxg[i - 1] / s * 192.0f);  // rintf == jnp.round (half-even)
            sparam[i] = pv;
            tot += pv;
        }
        sparam[32] = 192.0f - tot;
    }
    // DCT basis: basis[i][tx][ty]
    const float PI = 3.14159265358979323846f;
    const float INV_SQRT7 = 0.37796447300922722721f;
    const float SQRT2 = 1.41421356237309504880f;
    for (int idx = t; idx < 32 * 49; idx += 192) {
        int bi = idx / 49, k = idx % 49;
        int tx = k / 7, ty = k % 7;
        float fx = c_lowx[bi], fy = c_lowy[bi];
        float bx = cosf(PI * fx * (tx + 0.5f) / 7.0f) * INV_SQRT7;
        if (fx != 0.0f) bx *= SQRT2;
        float by = cosf(PI * fy * (ty + 0.5f) / 7.0f) * INV_SQRT7;
        if (fy != 0.0f) by *= SQRT2;
        sbasis[idx] = bx * by;
    }
    __syncthreads();

    // yin[c]: last segment i with param[i] <= c < param[i+1] wins (matches loop overwrite)
    {
        float cf = (float)t;
        int bid = -1;
        for (int i = 0; i < 32; i++)
            if (cf >= sparam[i] && cf < sparam[i + 1]) bid = i;
        float yv = 0.0f;
        if (bid >= 0) {
            const float* xpp = g_xp + (n * 192 + t) * 49;
            const float* bb = sbasis + bid * 49;
#pragma unroll
            for (int k = 0; k < 49; k++) yv = fmaf(xpp[k], bb[k], yv);
        }
        syin[t] = yv;
    }
    __syncthreads();

    // y[o] = sum_c w1d[o][c][1] * yin[c] + b1d[o]; BN; ReLU
    {
        float a = b1d[t];
        for (int c = 0; c < 192; c++) a = fmaf(g_w1dT[c * 192 + t], syin[c], a);
        float sc = bn1g[t] / sqrtf(bn1v[t] + 1e-5f);
        a = (a - bn1m[t]) * sc + bn1b[t];
        g_scale[n * 192 + t] = fmaxf(a, 0.0f);
    }
}

// ---------------------------------------------------------------------------
// Final kernel: out = x * (1 + scale[n,c]).  Traverses in REVERSE address
// order so early reads hit the tail of x still resident in L2 after pool_kernel.
// ---------------------------------------------------------------------------
__global__ __launch_bounds__(256) void final_kernel(
    const float* __restrict__ x, float* __restrict__ out)
{
    const float4* x4 = (const float4*)x;
    float4* o4 = (float4*)out;
    int stride = gridDim.x * blockDim.x;
    for (int i = blockIdx.x * blockDim.x + threadIdx.x; i < N4TOT; i += stride) {
        int r = N4TOT - 1 - i;
        int nc = r / 784;                       // 784 float4 per (n,c) plane
        float s = 1.0f + __ldg(&g_scale[nc]);
        float4 v = __ldg(x4 + r);
        v.x *= s; v.y *= s; v.z *= s; v.w *= s;
        o4[r] = v;
    }
}

// ---------------------------------------------------------------------------
// Launch. Inputs (metadata order): x, wg1, bn2_g, bn2_b, bn2_m, bn2_v,
//                                  wg2, bg2, beta, w1d, b1d, bn1_g, bn1_b, bn1_m, bn1_v
// ---------------------------------------------------------------------------
extern "C" void kernel_launch(void* const* d_in, const int* in_sizes, int n_in,
                              void* d_out, int out_size)
{
    const float* x     = (const float*)d_in[0];
    const float* wg1   = (const float*)d_in[1];
    const float* bn2g  = (const float*)d_in[2];
    const float* bn2b  = (const float*)d_in[3];
    const float* bn2m  = (const float*)d_in[4];
    const float* bn2v  = (const float*)d_in[5];
    const float* wg2   = (const float*)d_in[6];
    const float* bg2   = (const float*)d_in[7];
    const float* beta  = (const float*)d_in[8];
    const float* w1d   = (const float*)d_in[9];
    const float* b1d   = (const float*)d_in[10];
    const float* bn1g  = (const float*)d_in[11];
    const float* bn1b  = (const float*)d_in[12];
    const float* bn1m  = (const float*)d_in[13];
    const float* bn1v  = (const float*)d_in[14];
    float* out = (float*)d_out;

    gate_kernel<<<56, 448>>>(x, wg1, bn2g, bn2b, bn2m, bn2v);
    pool_kernel<<<2352, 256>>>(x, w1d);
    scale_kernel<<<64, 192>>>(wg2, bg2, beta, b1d, bn1g, bn1b, bn1m, bn1v);
    final_kernel<<<2368, 256>>>(x, out);
}